// round 1
// baseline (speedup 1.0000x reference)
#include <cuda_runtime.h>
#include <math.h>

// ---------------------------------------------------------------------------
// Problem: QuantumNATExtendedQML
//   conv1(1->8,3x3,SAME) -> BN -> relu -> maxpool2   (128x1x224x224)
//   conv2(8->16,3x3,SAME) -> BN -> relu -> maxpool2 -> spatial mean
//   feat[:, :4]  (=> only conv2 channels 0..3 matter!)
//   global standardize (ddof=1) * pi -> 4-qubit circuit -> batch-norm -> out
// Output: 128 x 4 float32
// ---------------------------------------------------------------------------

#define NB 128

// persistent device scratch (no cudaMalloc allowed)
__device__ double g_stats1[16];                 // sum[8], sumsq[8] of conv1 output
__device__ double g_stats2[8];                  // sum[4], sumsq[4] of conv2 output
__device__ float  g_a1[8], g_c1[8];             // bn1 affine: y*a + c
__device__ float  g_a2[4], g_c2[4];             // bn2 affine
__device__ float  g_h1[NB * 8 * 112 * 112];     // pooled conv1 output (51.4 MB)
__device__ float  g_y2[NB * 4 * 112 * 112];     // raw conv2 output, 4 ch (25.7 MB)
__device__ float  g_feat[NB * 4];               // per (n, c) spatial means

__device__ __forceinline__ float warp_sum(float v) {
#pragma unroll
    for (int o = 16; o > 0; o >>= 1) v += __shfl_xor_sync(0xffffffffu, v, o);
    return v;
}

// ---------------------------------------------------------------------------
__global__ void k_zero() {
    int t = threadIdx.x;
    if (t < 16) g_stats1[t] = 0.0;
    if (t < 8)  g_stats2[t] = 0.0;
}

// ---------------------------------------------------------------------------
// conv1 statistics pass: per-channel sum / sumsq of conv1(x)+bias over (N,H,W)
// grid (28, 128), block 256.  Each block: one image, 8 conv rows x 224 cols.
__global__ void k_conv1_stats(const float* __restrict__ x,
                              const float* __restrict__ w,
                              const float* __restrict__ bias) {
    __shared__ float tile[10][226];
    __shared__ double sacc[16];
    const int n = blockIdx.y, h0 = blockIdx.x * 8, tid = threadIdx.x;

    for (int i = tid; i < 10 * 226; i += 256) {
        int r = i / 226, c = i % 226;
        int hh = h0 - 1 + r, ww = c - 1;
        float v = 0.f;
        if (hh >= 0 && hh < 224 && ww >= 0 && ww < 224)
            v = x[((size_t)n * 224 + hh) * 224 + ww];
        tile[r][c] = v;
    }
    if (tid < 16) sacc[tid] = 0.0;

    float wr[72], br[8];
#pragma unroll
    for (int k = 0; k < 72; k++) wr[k] = w[k];
#pragma unroll
    for (int k = 0; k < 8; k++) br[k] = bias[k];
    __syncthreads();

    float s[8], q[8];
#pragma unroll
    for (int k = 0; k < 8; k++) { s[k] = 0.f; q[k] = 0.f; }

    for (int p = tid; p < 8 * 224; p += 256) {
        int r = p / 224, c = p % 224;
        float v[9];
#pragma unroll
        for (int kh = 0; kh < 3; kh++)
#pragma unroll
            for (int kw = 0; kw < 3; kw++)
                v[kh * 3 + kw] = tile[r + kh][c + kw];
#pragma unroll
        for (int oc = 0; oc < 8; oc++) {
            float y = br[oc];
#pragma unroll
            for (int k = 0; k < 9; k++) y = fmaf(wr[oc * 9 + k], v[k], y);
            s[oc] += y;
            q[oc] = fmaf(y, y, q[oc]);
        }
    }
#pragma unroll
    for (int oc = 0; oc < 8; oc++) {
        float ws = warp_sum(s[oc]);
        float wq = warp_sum(q[oc]);
        if ((tid & 31) == 0) {
            atomicAdd(&sacc[oc], (double)ws);
            atomicAdd(&sacc[8 + oc], (double)wq);
        }
    }
    __syncthreads();
    if (tid < 16) atomicAdd(&g_stats1[tid], sacc[tid]);
}

__global__ void k_fin1(const float* __restrict__ g, const float* __restrict__ b) {
    int c = threadIdx.x;           // 8 threads
    double N = (double)NB * 224.0 * 224.0;
    double mu = g_stats1[c] / N;
    double var = g_stats1[8 + c] / N - mu * mu;
    double a = (double)g[c] * rsqrt(var + 1e-5);
    g_a1[c] = (float)a;
    g_c1[c] = (float)((double)b[c] - mu * a);
}

// ---------------------------------------------------------------------------
// conv1 main pass: conv + bn + relu + 2x2 maxpool -> g_h1
// grid (28, 128), block 256. Each block: 8 conv rows -> 4 pooled rows x 112.
__global__ void k_conv1_main(const float* __restrict__ x,
                             const float* __restrict__ w,
                             const float* __restrict__ bias) {
    __shared__ float tile[10][226];
    const int n = blockIdx.y, h0 = blockIdx.x * 8, tid = threadIdx.x;

    for (int i = tid; i < 10 * 226; i += 256) {
        int r = i / 226, c = i % 226;
        int hh = h0 - 1 + r, ww = c - 1;
        float v = 0.f;
        if (hh >= 0 && hh < 224 && ww >= 0 && ww < 224)
            v = x[((size_t)n * 224 + hh) * 224 + ww];
        tile[r][c] = v;
    }

    // fold BN affine into the weights/bias:  bn(conv) = conv * a + (bias*a + c)
    float wr[72], br[8];
#pragma unroll
    for (int oc = 0; oc < 8; oc++) {
        float a = g_a1[oc];
        float cc = g_c1[oc];
#pragma unroll
        for (int k = 0; k < 9; k++) wr[oc * 9 + k] = w[oc * 9 + k] * a;
        br[oc] = fmaf(bias[oc], a, cc);
    }
    __syncthreads();

    for (int p = tid; p < 4 * 112; p += 256) {
        int pr = p / 112, pw = p % 112;
        float m[8];
#pragma unroll
        for (int oc = 0; oc < 8; oc++) m[oc] = -1e30f;
#pragma unroll
        for (int dy = 0; dy < 2; dy++)
#pragma unroll
            for (int dx = 0; dx < 2; dx++) {
                int r = 2 * pr + dy, c = 2 * pw + dx;
                float v[9];
#pragma unroll
                for (int kh = 0; kh < 3; kh++)
#pragma unroll
                    for (int kw = 0; kw < 3; kw++)
                        v[kh * 3 + kw] = tile[r + kh][c + kw];
#pragma unroll
                for (int oc = 0; oc < 8; oc++) {
                    float y = br[oc];
#pragma unroll
                    for (int k = 0; k < 9; k++) y = fmaf(wr[oc * 9 + k], v[k], y);
                    m[oc] = fmaxf(m[oc], y);
                }
            }
        int hh = blockIdx.x * 4 + pr;
#pragma unroll
        for (int oc = 0; oc < 8; oc++)
            g_h1[(((size_t)n * 8 + oc) * 112 + hh) * 112 + pw] = fmaxf(m[oc], 0.f);
    }
}

// ---------------------------------------------------------------------------
// conv2 (only output channels 0..3): compute raw y2 = conv+bias, store, and
// accumulate per-channel sum/sumsq.  grid (14, 128), block 224.
// Each thread: 1 row x 4 pixels (strided by 28 -> conflict-free lane access).
__global__ void k_conv2(const float* __restrict__ w2, const float* __restrict__ b2) {
    __shared__ float tile[8][10][114];
    __shared__ float4 wq[72];
    __shared__ float bsh[4];
    __shared__ double sacc[8];
    const int n = blockIdx.y, h0 = blockIdx.x * 8, tid = threadIdx.x;

    for (int i = tid; i < 8 * 10 * 114; i += 224) {
        int ic = i / 1140, rr = (i % 1140) / 114, c = i % 114;
        int hh = h0 - 1 + rr, ww = c - 1;
        float v = 0.f;
        if (hh >= 0 && hh < 112 && ww >= 0 && ww < 112)
            v = g_h1[(((size_t)n * 8 + ic) * 112 + hh) * 112 + ww];
        tile[ic][rr][c] = v;
    }
    if (tid < 72)  // w2 layout [16][8][3][3]; pack oc 0..3 per (ic,k)
        wq[tid] = make_float4(w2[tid], w2[72 + tid], w2[144 + tid], w2[216 + tid]);
    if (tid < 4) bsh[tid] = b2[tid];
    if (tid < 8) sacc[tid] = 0.0;
    __syncthreads();

    const int r = tid / 28, g = tid % 28;
    float a[4][4];
#pragma unroll
    for (int i = 0; i < 4; i++)
#pragma unroll
        for (int j = 0; j < 4; j++) a[i][j] = 0.f;

    for (int ic = 0; ic < 8; ic++) {
#pragma unroll
        for (int kh = 0; kh < 3; kh++) {
            float v[4][3];
#pragma unroll
            for (int p = 0; p < 4; p++)
#pragma unroll
                for (int kw = 0; kw < 3; kw++)
                    v[p][kw] = tile[ic][r + kh][g + 28 * p + kw];
#pragma unroll
            for (int kw = 0; kw < 3; kw++) {
                float4 wv = wq[ic * 9 + kh * 3 + kw];
#pragma unroll
                for (int p = 0; p < 4; p++) {
                    a[0][p] = fmaf(wv.x, v[p][kw], a[0][p]);
                    a[1][p] = fmaf(wv.y, v[p][kw], a[1][p]);
                    a[2][p] = fmaf(wv.z, v[p][kw], a[2][p]);
                    a[3][p] = fmaf(wv.w, v[p][kw], a[3][p]);
                }
            }
        }
    }

    float s[4] = {0.f, 0.f, 0.f, 0.f}, q[4] = {0.f, 0.f, 0.f, 0.f};
    const int hh = h0 + r;
#pragma unroll
    for (int oc = 0; oc < 4; oc++) {
#pragma unroll
        for (int p = 0; p < 4; p++) {
            float y = a[oc][p] + bsh[oc];
            s[oc] += y;
            q[oc] = fmaf(y, y, q[oc]);
            g_y2[(((size_t)n * 4 + oc) * 112 + hh) * 112 + (g + 28 * p)] = y;
        }
    }
#pragma unroll
    for (int oc = 0; oc < 4; oc++) {
        float ws = warp_sum(s[oc]);
        float wv = warp_sum(q[oc]);
        if ((tid & 31) == 0) {
            atomicAdd(&sacc[oc], (double)ws);
            atomicAdd(&sacc[4 + oc], (double)wv);
        }
    }
    __syncthreads();
    if (tid < 8) atomicAdd(&g_stats2[tid], sacc[tid]);
}

__global__ void k_fin2(const float* __restrict__ g, const float* __restrict__ b) {
    int c = threadIdx.x;           // 4 threads
    double N = (double)NB * 112.0 * 112.0;
    double mu = g_stats2[c] / N;
    double var = g_stats2[4 + c] / N - mu * mu;
    double a = (double)g[c] * rsqrt(var + 1e-5);
    g_a2[c] = (float)a;
    g_c2[c] = (float)((double)b[c] - mu * a);
}

// ---------------------------------------------------------------------------
// bn + relu + maxpool + spatial mean on stored y2.  grid (4, 128), block 256.
__global__ void k_pool_mean() {
    const int oc = blockIdx.x, n = blockIdx.y, tid = threadIdx.x;
    const float a = g_a2[oc], cc = g_c2[oc];
    const float* pl = &g_y2[((size_t)n * 4 + oc) * 112 * 112];
    float s = 0.f;
    for (int p = tid; p < 56 * 56; p += 256) {
        int pr = p / 56, pw = p % 56;
        const float* qp = pl + (2 * pr) * 112 + 2 * pw;
        float y0 = fmaf(qp[0], a, cc);
        float y1 = fmaf(qp[1], a, cc);
        float y2 = fmaf(qp[112], a, cc);
        float y3 = fmaf(qp[113], a, cc);
        float m = fmaxf(fmaxf(y0, y1), fmaxf(y2, y3));
        s += fmaxf(m, 0.f);
    }
    __shared__ float sm[8];
    float ws = warp_sum(s);
    if ((tid & 31) == 0) sm[tid >> 5] = ws;
    __syncthreads();
    if (tid == 0) {
        float t = 0.f;
#pragma unroll
        for (int i = 0; i < 8; i++) t += sm[i];
        g_feat[n * 4 + oc] = t / 3136.f;
    }
}

// ---------------------------------------------------------------------------
// Quantum circuit: 4 qubits -> 16 complex amplitudes in registers per thread.
// Index bit for qubit q (jnp C-order, qubit 0 most significant): mask = 8 >> q.
template <int Q>
__device__ __forceinline__ void ry_gate(float2* st, float t) {
    float s, c;
    sincosf(0.5f * t, &s, &c);
    const int m = 8 >> Q;
#pragma unroll
    for (int i = 0; i < 16; i++)
        if (!(i & m)) {
            float2 a0 = st[i], a1 = st[i | m];
            st[i]     = make_float2(c * a0.x - s * a1.x, c * a0.y - s * a1.y);
            st[i | m] = make_float2(s * a0.x + c * a1.x, s * a0.y + c * a1.y);
        }
}
template <int Q>
__device__ __forceinline__ void rz_gate(float2* st, float t) {
    float s, c;
    sincosf(0.5f * t, &s, &c);
    const int m = 8 >> Q;
#pragma unroll
    for (int i = 0; i < 16; i++)
        if (!(i & m)) {
            float2 a0 = st[i], a1 = st[i | m];
            st[i]     = make_float2(c * a0.x + s * a0.y, c * a0.y - s * a0.x); // * e^{-it/2}
            st[i | m] = make_float2(c * a1.x - s * a1.y, c * a1.y + s * a1.x); // * e^{+it/2}
        }
}
template <int Q>
__device__ __forceinline__ void rx_gate(float2* st, float t) {
    float s, c;
    sincosf(0.5f * t, &s, &c);
    const int m = 8 >> Q;
#pragma unroll
    for (int i = 0; i < 16; i++)
        if (!(i & m)) {
            float2 a0 = st[i], a1 = st[i | m];
            st[i]     = make_float2(c * a0.x + s * a1.y, c * a0.y - s * a1.x);
            st[i | m] = make_float2(c * a1.x + s * a0.y, c * a1.y - s * a0.x);
        }
}
template <int C, int T>
__device__ __forceinline__ void cnot_gate(float2* st) {
    const int mc = 8 >> C, mt = 8 >> T;
#pragma unroll
    for (int i = 0; i < 16; i++)
        if ((i & mc) && !(i & mt)) {
            float2 tmp = st[i];
            st[i] = st[i | mt];
            st[i | mt] = tmp;
        }
}

__global__ void k_final(const float* __restrict__ theta, const float* __restrict__ rho,
                        const float* __restrict__ ng, const float* __restrict__ nb,
                        float* __restrict__ out) {
    const int tid = threadIdx.x;   // 128 threads, one per batch element
    float f[4];
#pragma unroll
    for (int j = 0; j < 4; j++) f[j] = g_feat[tid * 4 + j];

    // global standardize over all 512 feat values, ddof=1
    __shared__ double ssum, ssq;
    if (tid == 0) { ssum = 0.0; ssq = 0.0; }
    __syncthreads();
    float lf = f[0] + f[1] + f[2] + f[3];
    float lq = f[0] * f[0] + f[1] * f[1] + f[2] * f[2] + f[3] * f[3];
    float ws = warp_sum(lf), wq = warp_sum(lq);
    if ((tid & 31) == 0) { atomicAdd(&ssum, (double)ws); atomicAdd(&ssq, (double)wq); }
    __syncthreads();
    double mean = ssum / 512.0;
    double var1 = (ssq - 512.0 * mean * mean) / 511.0;
    if (var1 < 0.0) var1 = 0.0;
    float scale = (float)(3.14159265358979323846 / (sqrt(var1) + 1e-6));
    float sc[4];
#pragma unroll
    for (int j = 0; j < 4; j++) sc[j] = (float)((double)f[j] - mean) * scale;

    // circuit
    float2 st[16];
#pragma unroll
    for (int i = 0; i < 16; i++) st[i] = make_float2(0.f, 0.f);
    st[0].x = 1.f;

    ry_gate<0>(st, sc[0]); ry_gate<1>(st, sc[1]); ry_gate<2>(st, sc[2]); ry_gate<3>(st, sc[3]);

    ry_gate<0>(st, theta[0]);  rz_gate<0>(st, theta[1]);  rx_gate<0>(st, theta[2]);
    ry_gate<1>(st, theta[3]);  rz_gate<1>(st, theta[4]);  rx_gate<1>(st, theta[5]);
    ry_gate<2>(st, theta[6]);  rz_gate<2>(st, theta[7]);  rx_gate<2>(st, theta[8]);
    ry_gate<3>(st, theta[9]);  rz_gate<3>(st, theta[10]); rx_gate<3>(st, theta[11]);

    cnot_gate<0, 1>(st); cnot_gate<1, 2>(st); cnot_gate<2, 3>(st);

    ry_gate<0>(st, rho[0]);  rz_gate<0>(st, rho[1]);  rx_gate<0>(st, rho[2]);
    ry_gate<1>(st, rho[3]);  rz_gate<1>(st, rho[4]);  rx_gate<1>(st, rho[5]);
    ry_gate<2>(st, rho[6]);  rz_gate<2>(st, rho[7]);  rx_gate<2>(st, rho[8]);
    ry_gate<3>(st, rho[9]);  rz_gate<3>(st, rho[10]); rx_gate<3>(st, rho[11]);

    cnot_gate<1, 0>(st); cnot_gate<2, 1>(st); cnot_gate<3, 2>(st);

    float pr[16];
#pragma unroll
    for (int i = 0; i < 16; i++) pr[i] = st[i].x * st[i].x + st[i].y * st[i].y;

    float e[4];
#pragma unroll
    for (int q = 0; q < 4; q++) {
        const int m = 8 >> q;
        float acc = 0.f;
#pragma unroll
        for (int i = 0; i < 16; i++) acc += (i & m) ? -pr[i] : pr[i];
        e[q] = acc;
    }

    // final batch-norm over the 128 batch elements, per output column
    __shared__ double s1, s2;
#pragma unroll
    for (int j = 0; j < 4; j++) {
        if (tid == 0) { s1 = 0.0; s2 = 0.0; }
        __syncthreads();
        float v = e[j];
        float w1 = warp_sum(v), w2 = warp_sum(v * v);
        if ((tid & 31) == 0) { atomicAdd(&s1, (double)w1); atomicAdd(&s2, (double)w2); }
        __syncthreads();
        double mu = s1 / 128.0;
        double vv = s2 / 128.0 - mu * mu;
        out[tid * 4 + j] =
            (float)(((double)v - mu) * rsqrt(vv + 1e-5) * (double)ng[j] + (double)nb[j]);
        __syncthreads();
    }
}

// ---------------------------------------------------------------------------
extern "C" void kernel_launch(void* const* d_in, const int* in_sizes, int n_in,
                              void* d_out, int out_size) {
    const float* x     = (const float*)d_in[0];
    const float* w1    = (const float*)d_in[1];
    const float* b1    = (const float*)d_in[2];
    const float* bn1g  = (const float*)d_in[3];
    const float* bn1b  = (const float*)d_in[4];
    const float* w2    = (const float*)d_in[5];
    const float* b2    = (const float*)d_in[6];
    const float* bn2g  = (const float*)d_in[7];
    const float* bn2b  = (const float*)d_in[8];
    const float* theta = (const float*)d_in[9];
    const float* rho   = (const float*)d_in[10];
    const float* ng    = (const float*)d_in[11];
    const float* nbp   = (const float*)d_in[12];
    float* out = (float*)d_out;

    k_zero<<<1, 32>>>();
    k_conv1_stats<<<dim3(28, NB), 256>>>(x, w1, b1);
    k_fin1<<<1, 8>>>(bn1g, bn1b);
    k_conv1_main<<<dim3(28, NB), 256>>>(x, w1, b1);
    k_conv2<<<dim3(14, NB), 224>>>(w2, b2);
    k_fin2<<<1, 4>>>(bn2g, bn2b);
    k_pool_mean<<<dim3(4, NB), 256>>>();
    k_final<<<1, 128>>>(theta, rho, ng, nbp, out);
}

// round 2
// speedup vs baseline: 1.5815x; 1.5815x over previous
#include <cuda_runtime.h>
#include <math.h>

// ---------------------------------------------------------------------------
// QuantumNATExtendedQML — R1: column-strip convs, channel-last layouts,
// partial-sum stats (no zero kernel), vectorized stores.
// ---------------------------------------------------------------------------

#define NB 128

// persistent device scratch (no cudaMalloc allowed)
__device__ double g_p1[896 * 16];                        // conv1 per-block partials
__device__ double g_p2[1792 * 8];                        // conv2 per-block partials
__device__ __align__(16) float g_a1[8], g_c1[8];         // bn1 affine
__device__ __align__(16) float g_a2[4], g_c2[4];         // bn2 affine
__device__ __align__(16) float g_h1[NB * 112 * 112 * 8]; // pooled conv1, ch-last
__device__ __align__(16) float g_y2[NB * 112 * 112 * 4]; // raw conv2, ch-last
__device__ __align__(16) float g_feat[NB * 4];

__device__ __forceinline__ float warp_sum(float v) {
#pragma unroll
    for (int o = 16; o > 0; o >>= 1) v += __shfl_xor_sync(0xffffffffu, v, o);
    return v;
}

// ---------------------------------------------------------------------------
// conv1 stats: grid(7, 128), block 256 (224 compute threads, 1 per column).
// Stripe of 32 conv rows; rolling 3x3 window; per-block partial sums.
__global__ void __launch_bounds__(256) k_conv1_stats(const float* __restrict__ x,
                                                     const float* __restrict__ w,
                                                     const float* __restrict__ bias) {
    __shared__ float tile[34][226];
    __shared__ double sacc[16];
    const int n = blockIdx.y, h0 = blockIdx.x * 32, tid = threadIdx.x;

    const float* xim = x + (size_t)n * 224 * 224;
    for (int i = tid; i < 34 * 226; i += 256) {
        int r = i / 226, c = i % 226;
        int hh = h0 - 1 + r, ww = c - 1;
        float v = 0.f;
        if (hh >= 0 && hh < 224 && ww >= 0 && ww < 224) v = xim[hh * 224 + ww];
        tile[r][c] = v;
    }
    if (tid < 16) sacc[tid] = 0.0;

    float s[8], q[8];
#pragma unroll
    for (int k = 0; k < 8; k++) { s[k] = 0.f; q[k] = 0.f; }

    if (tid < 224) {
        float wr[72], br[8];
#pragma unroll
        for (int k = 0; k < 72; k++) wr[k] = w[k];
#pragma unroll
        for (int k = 0; k < 8; k++) br[k] = bias[k];
        __syncthreads();

        const int c = tid;
        float v0a = tile[0][c], v0b = tile[0][c + 1], v0c = tile[0][c + 2];
        float v1a = tile[1][c], v1b = tile[1][c + 1], v1c = tile[1][c + 2];
#pragma unroll 2
        for (int r = 0; r < 32; r++) {
            float v2a = tile[r + 2][c], v2b = tile[r + 2][c + 1], v2c = tile[r + 2][c + 2];
#pragma unroll
            for (int oc = 0; oc < 8; oc++) {
                const float* wk = &wr[oc * 9];
                float y = br[oc];
                y = fmaf(wk[0], v0a, y); y = fmaf(wk[1], v0b, y); y = fmaf(wk[2], v0c, y);
                y = fmaf(wk[3], v1a, y); y = fmaf(wk[4], v1b, y); y = fmaf(wk[5], v1c, y);
                y = fmaf(wk[6], v2a, y); y = fmaf(wk[7], v2b, y); y = fmaf(wk[8], v2c, y);
                s[oc] += y;
                q[oc] = fmaf(y, y, q[oc]);
            }
            v0a = v1a; v0b = v1b; v0c = v1c;
            v1a = v2a; v1b = v2b; v1c = v2c;
        }
    } else {
        __syncthreads();
    }

#pragma unroll
    for (int oc = 0; oc < 8; oc++) {
        float ws = warp_sum(s[oc]);
        float wq = warp_sum(q[oc]);
        if ((tid & 31) == 0) {
            atomicAdd(&sacc[oc], (double)ws);
            atomicAdd(&sacc[8 + oc], (double)wq);
        }
    }
    __syncthreads();
    if (tid < 16) g_p1[(size_t)(blockIdx.y * 7 + blockIdx.x) * 16 + tid] = sacc[tid];
}

__global__ void k_fin1(const float* __restrict__ g, const float* __restrict__ b) {
    __shared__ double red[128];
    const int tid = threadIdx.x;
    const int st = tid & 15, ch = tid >> 4;
    double s = 0.0;
    for (int i = ch; i < 896; i += 8) s += g_p1[i * 16 + st];
    red[tid] = s;
    __syncthreads();
    if (tid < 16) {
        double t = red[tid];
#pragma unroll
        for (int j = 1; j < 8; j++) t += red[j * 16 + tid];
        red[tid] = t;
    }
    __syncthreads();
    if (tid < 8) {
        double N = 128.0 * 224.0 * 224.0;
        double mu = red[tid] / N;
        double var = red[8 + tid] / N - mu * mu;
        double a = (double)g[tid] * rsqrt(var + 1e-5);
        g_a1[tid] = (float)a;
        g_c1[tid] = (float)((double)b[tid] - mu * a);
    }
}

// ---------------------------------------------------------------------------
// conv1 main: conv+bn+relu+pool -> h1 (channel-last).
// grid(8, 128), block 128 (112 compute threads, 1 per pooled column).
// Each thread: 14 pooled rows, rolling 4x4 window, BN folded into weights.
__global__ void __launch_bounds__(128) k_conv1_main(const float* __restrict__ x,
                                                    const float* __restrict__ w,
                                                    const float* __restrict__ bias) {
    __shared__ float tile[30][226];
    const int n = blockIdx.y, tid = threadIdx.x;
    const int h0in = blockIdx.x * 28 - 1;  // first input row of tile

    const float* xim = x + (size_t)n * 224 * 224;
    for (int i = tid; i < 30 * 226; i += 128) {
        int r = i / 226, c = i % 226;
        int hh = h0in + r, ww = c - 1;
        float v = 0.f;
        if (hh >= 0 && hh < 224 && ww >= 0 && ww < 224) v = xim[hh * 224 + ww];
        tile[r][c] = v;
    }
    __syncthreads();

    if (tid >= 112) return;

    float wf[72], br[8];
#pragma unroll
    for (int oc = 0; oc < 8; oc++) {
        float a = g_a1[oc], cc = g_c1[oc];
#pragma unroll
        for (int k = 0; k < 9; k++) wf[oc * 9 + k] = w[oc * 9 + k] * a;
        br[oc] = fmaf(bias[oc], a, cc);
    }

    const int c0 = 2 * tid;
    float v[4][4];
#pragma unroll
    for (int j = 0; j < 2; j++)
#pragma unroll
        for (int i = 0; i < 4; i++) v[j][i] = tile[j][c0 + i];

    float* outp = &g_h1[(((size_t)n * 112 + blockIdx.x * 14) * 112 + tid) * 8];

#pragma unroll 1
    for (int pr = 0; pr < 14; pr++) {
#pragma unroll
        for (int i = 0; i < 4; i++) {
            v[2][i] = tile[2 * pr + 2][c0 + i];
            v[3][i] = tile[2 * pr + 3][c0 + i];
        }
        float m[8];
#pragma unroll
        for (int oc = 0; oc < 8; oc++) m[oc] = -3.4e38f;
#pragma unroll
        for (int dy = 0; dy < 2; dy++)
#pragma unroll
            for (int dx = 0; dx < 2; dx++) {
#pragma unroll
                for (int oc = 0; oc < 8; oc++) {
                    const float* wk = &wf[oc * 9];
                    float z = br[oc];
                    z = fmaf(wk[0], v[dy + 0][dx + 0], z);
                    z = fmaf(wk[1], v[dy + 0][dx + 1], z);
                    z = fmaf(wk[2], v[dy + 0][dx + 2], z);
                    z = fmaf(wk[3], v[dy + 1][dx + 0], z);
                    z = fmaf(wk[4], v[dy + 1][dx + 1], z);
                    z = fmaf(wk[5], v[dy + 1][dx + 2], z);
                    z = fmaf(wk[6], v[dy + 2][dx + 0], z);
                    z = fmaf(wk[7], v[dy + 2][dx + 1], z);
                    z = fmaf(wk[8], v[dy + 2][dx + 2], z);
                    m[oc] = fmaxf(m[oc], z);
                }
            }
        float4 o0 = make_float4(fmaxf(m[0], 0.f), fmaxf(m[1], 0.f),
                                fmaxf(m[2], 0.f), fmaxf(m[3], 0.f));
        float4 o1 = make_float4(fmaxf(m[4], 0.f), fmaxf(m[5], 0.f),
                                fmaxf(m[6], 0.f), fmaxf(m[7], 0.f));
        *(float4*)outp = o0;
        *(float4*)(outp + 4) = o1;
        outp += 112 * 8;
#pragma unroll
        for (int i = 0; i < 4; i++) { v[0][i] = v[2][i]; v[1][i] = v[3][i]; }
    }
}

// ---------------------------------------------------------------------------
// conv2 (oc 0..3 only): raw y2 (channel-last) + per-block partial stats.
// grid(14, 128), block 224.  Thread: 1 row x 4 pixels (stride 28).
__global__ void __launch_bounds__(224) k_conv2(const float* __restrict__ w2,
                                               const float* __restrict__ b2) {
    __shared__ float tile[8][10][114];
    __shared__ float4 wq[72];
    __shared__ float bsh[4];
    __shared__ double sacc[8];
    const int n = blockIdx.y, h0 = blockIdx.x * 8, tid = threadIdx.x;

    for (int i = tid; i < 10 * 114; i += 224) {
        int r = i / 114, c = i % 114;
        int hh = h0 - 1 + r, ww = c - 1;
        float4 p0 = make_float4(0.f, 0.f, 0.f, 0.f), p1 = p0;
        if (hh >= 0 && hh < 112 && ww >= 0 && ww < 112) {
            const float4* hp = (const float4*)&g_h1[(((size_t)n * 112 + hh) * 112 + ww) * 8];
            p0 = hp[0]; p1 = hp[1];
        }
        tile[0][r][c] = p0.x; tile[1][r][c] = p0.y; tile[2][r][c] = p0.z; tile[3][r][c] = p0.w;
        tile[4][r][c] = p1.x; tile[5][r][c] = p1.y; tile[6][r][c] = p1.z; tile[7][r][c] = p1.w;
    }
    if (tid < 72)  // w2 layout [16][8][3][3]; pack oc 0..3 per (ic,k)
        wq[tid] = make_float4(w2[tid], w2[72 + tid], w2[144 + tid], w2[216 + tid]);
    if (tid < 4) bsh[tid] = b2[tid];
    if (tid < 8) sacc[tid] = 0.0;
    __syncthreads();

    const int r = tid / 28, g = tid % 28;
    float a[4][4];
#pragma unroll
    for (int i = 0; i < 4; i++)
#pragma unroll
        for (int j = 0; j < 4; j++) a[i][j] = 0.f;

#pragma unroll 1
    for (int ic = 0; ic < 8; ic++) {
#pragma unroll
        for (int kh = 0; kh < 3; kh++) {
            float v[4][3];
#pragma unroll
            for (int p = 0; p < 4; p++)
#pragma unroll
                for (int kw = 0; kw < 3; kw++)
                    v[p][kw] = tile[ic][r + kh][g + 28 * p + kw];
#pragma unroll
            for (int kw = 0; kw < 3; kw++) {
                float4 wv = wq[ic * 9 + kh * 3 + kw];
#pragma unroll
                for (int p = 0; p < 4; p++) {
                    a[0][p] = fmaf(wv.x, v[p][kw], a[0][p]);
                    a[1][p] = fmaf(wv.y, v[p][kw], a[1][p]);
                    a[2][p] = fmaf(wv.z, v[p][kw], a[2][p]);
                    a[3][p] = fmaf(wv.w, v[p][kw], a[3][p]);
                }
            }
        }
    }

    float s[4] = {0.f, 0.f, 0.f, 0.f}, q[4] = {0.f, 0.f, 0.f, 0.f};
    const int hh = h0 + r;
#pragma unroll
    for (int p = 0; p < 4; p++) {
        float y0 = a[0][p] + bsh[0];
        float y1 = a[1][p] + bsh[1];
        float y2 = a[2][p] + bsh[2];
        float y3 = a[3][p] + bsh[3];
        s[0] += y0; q[0] = fmaf(y0, y0, q[0]);
        s[1] += y1; q[1] = fmaf(y1, y1, q[1]);
        s[2] += y2; q[2] = fmaf(y2, y2, q[2]);
        s[3] += y3; q[3] = fmaf(y3, y3, q[3]);
        *(float4*)&g_y2[(((size_t)n * 112 + hh) * 112 + (g + 28 * p)) * 4] =
            make_float4(y0, y1, y2, y3);
    }
#pragma unroll
    for (int oc = 0; oc < 4; oc++) {
        float ws = warp_sum(s[oc]);
        float wv = warp_sum(q[oc]);
        if ((tid & 31) == 0) {
            atomicAdd(&sacc[oc], (double)ws);
            atomicAdd(&sacc[4 + oc], (double)wv);
        }
    }
    __syncthreads();
    if (tid < 8) g_p2[(size_t)(blockIdx.y * 14 + blockIdx.x) * 8 + tid] = sacc[tid];
}

__global__ void k_fin2(const float* __restrict__ g, const float* __restrict__ b) {
    __shared__ double red[128];
    const int tid = threadIdx.x;
    const int st = tid & 7, ch = tid >> 3;
    double s = 0.0;
    for (int i = ch; i < 1792; i += 16) s += g_p2[i * 8 + st];
    red[tid] = s;
    __syncthreads();
    if (tid < 8) {
        double t = red[tid];
#pragma unroll
        for (int j = 1; j < 16; j++) t += red[j * 8 + tid];
        red[tid] = t;
    }
    __syncthreads();
    if (tid < 4) {
        double N = 128.0 * 112.0 * 112.0;
        double mu = red[tid] / N;
        double var = red[4 + tid] / N - mu * mu;
        double a = (double)g[tid] * rsqrt(var + 1e-5);
        g_a2[tid] = (float)a;
        g_c2[tid] = (float)((double)b[tid] - mu * a);
    }
}

// ---------------------------------------------------------------------------
// bn + relu + maxpool + spatial mean on stored y2 (channel-last).
// grid(128), block 256.
__global__ void k_pool_mean() {
    const int n = blockIdx.x, tid = threadIdx.x;
    const float4 av = *(const float4*)g_a2;
    const float4 cv = *(const float4*)g_c2;
    const float* base = &g_y2[(size_t)n * 112 * 112 * 4];
    float4 acc = make_float4(0.f, 0.f, 0.f, 0.f);

    for (int p = tid; p < 56 * 56; p += 256) {
        int pr = p / 56, pw = p % 56;
        const float4* q0 = (const float4*)(base + ((2 * pr) * 112 + 2 * pw) * 4);
        const float4* q1 = (const float4*)(base + ((2 * pr + 1) * 112 + 2 * pw) * 4);
        float4 y00 = q0[0], y01 = q0[1], y10 = q1[0], y11 = q1[1];
        float4 m;
        m.x = fmaxf(fmaxf(fmaf(y00.x, av.x, cv.x), fmaf(y01.x, av.x, cv.x)),
                    fmaxf(fmaf(y10.x, av.x, cv.x), fmaf(y11.x, av.x, cv.x)));
        m.y = fmaxf(fmaxf(fmaf(y00.y, av.y, cv.y), fmaf(y01.y, av.y, cv.y)),
                    fmaxf(fmaf(y10.y, av.y, cv.y), fmaf(y11.y, av.y, cv.y)));
        m.z = fmaxf(fmaxf(fmaf(y00.z, av.z, cv.z), fmaf(y01.z, av.z, cv.z)),
                    fmaxf(fmaf(y10.z, av.z, cv.z), fmaf(y11.z, av.z, cv.z)));
        m.w = fmaxf(fmaxf(fmaf(y00.w, av.w, cv.w), fmaf(y01.w, av.w, cv.w)),
                    fmaxf(fmaf(y10.w, av.w, cv.w), fmaf(y11.w, av.w, cv.w)));
        acc.x += fmaxf(m.x, 0.f);
        acc.y += fmaxf(m.y, 0.f);
        acc.z += fmaxf(m.z, 0.f);
        acc.w += fmaxf(m.w, 0.f);
    }
    __shared__ float4 sm[8];
    acc.x = warp_sum(acc.x); acc.y = warp_sum(acc.y);
    acc.z = warp_sum(acc.z); acc.w = warp_sum(acc.w);
    if ((tid & 31) == 0) sm[tid >> 5] = acc;
    __syncthreads();
    if (tid == 0) {
        float4 t = make_float4(0.f, 0.f, 0.f, 0.f);
#pragma unroll
        for (int i = 0; i < 8; i++) {
            t.x += sm[i].x; t.y += sm[i].y; t.z += sm[i].z; t.w += sm[i].w;
        }
        *(float4*)&g_feat[n * 4] =
            make_float4(t.x / 3136.f, t.y / 3136.f, t.z / 3136.f, t.w / 3136.f);
    }
}

// ---------------------------------------------------------------------------
// Quantum circuit (unchanged from passing R0 kernel).
template <int Q>
__device__ __forceinline__ void ry_gate(float2* st, float t) {
    float s, c;
    sincosf(0.5f * t, &s, &c);
    const int m = 8 >> Q;
#pragma unroll
    for (int i = 0; i < 16; i++)
        if (!(i & m)) {
            float2 a0 = st[i], a1 = st[i | m];
            st[i]     = make_float2(c * a0.x - s * a1.x, c * a0.y - s * a1.y);
            st[i | m] = make_float2(s * a0.x + c * a1.x, s * a0.y + c * a1.y);
        }
}
template <int Q>
__device__ __forceinline__ void rz_gate(float2* st, float t) {
    float s, c;
    sincosf(0.5f * t, &s, &c);
    const int m = 8 >> Q;
#pragma unroll
    for (int i = 0; i < 16; i++)
        if (!(i & m)) {
            float2 a0 = st[i], a1 = st[i | m];
            st[i]     = make_float2(c * a0.x + s * a0.y, c * a0.y - s * a0.x);
            st[i | m] = make_float2(c * a1.x - s * a1.y, c * a1.y + s * a1.x);
        }
}
template <int Q>
__device__ __forceinline__ void rx_gate(float2* st, float t) {
    float s, c;
    sincosf(0.5f * t, &s, &c);
    const int m = 8 >> Q;
#pragma unroll
    for (int i = 0; i < 16; i++)
        if (!(i & m)) {
            float2 a0 = st[i], a1 = st[i | m];
            st[i]     = make_float2(c * a0.x + s * a1.y, c * a0.y - s * a1.x);
            st[i | m] = make_float2(c * a1.x + s * a0.y, c * a1.y - s * a0.x);
        }
}
template <int C, int T>
__device__ __forceinline__ void cnot_gate(float2* st) {
    const int mc = 8 >> C, mt = 8 >> T;
#pragma unroll
    for (int i = 0; i < 16; i++)
        if ((i & mc) && !(i & mt)) {
            float2 tmp = st[i];
            st[i] = st[i | mt];
            st[i | mt] = tmp;
        }
}

__global__ void k_final(const float* __restrict__ theta, const float* __restrict__ rho,
                        const float* __restrict__ ng, const float* __restrict__ nb,
                        float* __restrict__ out) {
    const int tid = threadIdx.x;  // 128 threads, one per batch element
    float f[4];
#pragma unroll
    for (int j = 0; j < 4; j++) f[j] = g_feat[tid * 4 + j];

    __shared__ double ssum, ssq;
    if (tid == 0) { ssum = 0.0; ssq = 0.0; }
    __syncthreads();
    float lf = f[0] + f[1] + f[2] + f[3];
    float lq = f[0] * f[0] + f[1] * f[1] + f[2] * f[2] + f[3] * f[3];
    float ws = warp_sum(lf), wq = warp_sum(lq);
    if ((tid & 31) == 0) { atomicAdd(&ssum, (double)ws); atomicAdd(&ssq, (double)wq); }
    __syncthreads();
    double mean = ssum / 512.0;
    double var1 = (ssq - 512.0 * mean * mean) / 511.0;
    if (var1 < 0.0) var1 = 0.0;
    float scale = (float)(3.14159265358979323846 / (sqrt(var1) + 1e-6));
    float sc[4];
#pragma unroll
    for (int j = 0; j < 4; j++) sc[j] = (float)((double)f[j] - mean) * scale;

    float2 st[16];
#pragma unroll
    for (int i = 0; i < 16; i++) st[i] = make_float2(0.f, 0.f);
    st[0].x = 1.f;

    ry_gate<0>(st, sc[0]); ry_gate<1>(st, sc[1]); ry_gate<2>(st, sc[2]); ry_gate<3>(st, sc[3]);

    ry_gate<0>(st, theta[0]);  rz_gate<0>(st, theta[1]);  rx_gate<0>(st, theta[2]);
    ry_gate<1>(st, theta[3]);  rz_gate<1>(st, theta[4]);  rx_gate<1>(st, theta[5]);
    ry_gate<2>(st, theta[6]);  rz_gate<2>(st, theta[7]);  rx_gate<2>(st, theta[8]);
    ry_gate<3>(st, theta[9]);  rz_gate<3>(st, theta[10]); rx_gate<3>(st, theta[11]);

    cnot_gate<0, 1>(st); cnot_gate<1, 2>(st); cnot_gate<2, 3>(st);

    ry_gate<0>(st, rho[0]);  rz_gate<0>(st, rho[1]);  rx_gate<0>(st, rho[2]);
    ry_gate<1>(st, rho[3]);  rz_gate<1>(st, rho[4]);  rx_gate<1>(st, rho[5]);
    ry_gate<2>(st, rho[6]);  rz_gate<2>(st, rho[7]);  rx_gate<2>(st, rho[8]);
    ry_gate<3>(st, rho[9]);  rz_gate<3>(st, rho[10]); rx_gate<3>(st, rho[11]);

    cnot_gate<1, 0>(st); cnot_gate<2, 1>(st); cnot_gate<3, 2>(st);

    float pr[16];
#pragma unroll
    for (int i = 0; i < 16; i++) pr[i] = st[i].x * st[i].x + st[i].y * st[i].y;

    float e[4];
#pragma unroll
    for (int q = 0; q < 4; q++) {
        const int m = 8 >> q;
        float acc = 0.f;
#pragma unroll
        for (int i = 0; i < 16; i++) acc += (i & m) ? -pr[i] : pr[i];
        e[q] = acc;
    }

    __shared__ double s1, s2;
#pragma unroll
    for (int j = 0; j < 4; j++) {
        if (tid == 0) { s1 = 0.0; s2 = 0.0; }
        __syncthreads();
        float v = e[j];
        float w1 = warp_sum(v), w2 = warp_sum(v * v);
        if ((tid & 31) == 0) { atomicAdd(&s1, (double)w1); atomicAdd(&s2, (double)w2); }
        __syncthreads();
        double mu = s1 / 128.0;
        double vv = s2 / 128.0 - mu * mu;
        out[tid * 4 + j] =
            (float)(((double)v - mu) * rsqrt(vv + 1e-5) * (double)ng[j] + (double)nb[j]);
        __syncthreads();
    }
}

// ---------------------------------------------------------------------------
extern "C" void kernel_launch(void* const* d_in, const int* in_sizes, int n_in,
                              void* d_out, int out_size) {
    const float* x     = (const float*)d_in[0];
    const float* w1    = (const float*)d_in[1];
    const float* b1    = (const float*)d_in[2];
    const float* bn1g  = (const float*)d_in[3];
    const float* bn1b  = (const float*)d_in[4];
    const float* w2    = (const float*)d_in[5];
    const float* b2    = (const float*)d_in[6];
    const float* bn2g  = (const float*)d_in[7];
    const float* bn2b  = (const float*)d_in[8];
    const float* theta = (const float*)d_in[9];
    const float* rho   = (const float*)d_in[10];
    const float* ng    = (const float*)d_in[11];
    const float* nbp   = (const float*)d_in[12];
    float* out = (float*)d_out;

    k_conv1_stats<<<dim3(7, NB), 256>>>(x, w1, b1);
    k_fin1<<<1, 128>>>(bn1g, bn1b);
    k_conv1_main<<<dim3(8, NB), 128>>>(x, w1, b1);
    k_conv2<<<dim3(14, NB), 224>>>(w2, b2);
    k_fin2<<<1, 128>>>(bn2g, bn2b);
    k_pool_mean<<<128, 256>>>();
    k_final<<<1, 128>>>(theta, rho, ng, nbp, out);
}